// round 11
// baseline (speedup 1.0000x reference)
#include <cuda_runtime.h>
#include <cstdint>

// DySepConvAtten v11: two-kernel split at occupancy 3.
// K1: dy = Q@W+b (4 K-chunks) -> pw/dw scratch.
// K3: c-split (2 CTAs/batch), fused conv + GEMM; last CTA per batch does LN.
#define NROW 100
#define CDIM 256
#define JDIM 103
#define BMAX 512

__device__ float g_pw[BMAX * 104 * 104 + 4096];   // [b][n(104)][m(104)], zero-padded
__device__ float g_dw[BMAX * 100 * 4];            // [b][m][4]
__device__ float g_ps[BMAX * 2 * 112];            // per-half row sums
__device__ float g_pq[BMAX * 2 * 112];            // per-half row sumsq
__device__ int   g_flag[BMAX];                    // arrival counter (self-resetting)

static __device__ __forceinline__ uint32_t tf32c(float f) {
    uint32_t u; asm("cvt.rna.tf32.f32 %0, %1;" : "=r"(u) : "f"(f)); return u;
}
static __device__ __forceinline__ float tf32f(float f) {
    return __uint_as_float(tf32c(f));
}
static __device__ __forceinline__ void mma8(float* d, uint4 a, uint2 b) {
    asm volatile(
        "mma.sync.aligned.m16n8k8.row.col.f32.tf32.tf32.f32 "
        "{%0,%1,%2,%3}, {%4,%5,%6,%7}, {%8,%9}, {%0,%1,%2,%3};"
        : "+f"(d[0]), "+f"(d[1]), "+f"(d[2]), "+f"(d[3])
        : "r"(a.x), "r"(a.y), "r"(a.z), "r"(a.w), "r"(b.x), "r"(b.y));
}

// ================= K1: dy = Q @ W + b  (4 chunks of K=64) =================
// smem: region0 [0..10800): sQ [100][68]=6800 (stride 68, mod32=4) / dyBuf [100][108]
//       sW [64][104]=6656 @10800 (stride 104, mod32=8) ; bias 104 @17456
#define SQS2    68
#define DYS     108
#define K1_SW   10800
#define K1_BIAS 17456
#define K1_F    17560   // 70,240 B -> occ 3

__global__ void __launch_bounds__(256, 3)
k1_gemm(const float* __restrict__ query, const float* __restrict__ Wwl,
        const float* __restrict__ bwl)
{
    extern __shared__ float sm[];
    const uint32_t* smu = (const uint32_t*)sm;
    const int b = blockIdx.x, tid = threadIdx.x;
    const int w = tid >> 5, lane = tid & 31;
    const int lg = lane >> 2, lt = lane & 3;
    const float* qg = query + (size_t)b * (NROW * CDIM);

    if (tid < 104) sm[K1_BIAS + tid] = (tid < JDIM) ? bwl[tid] : 0.0f;

    float dA[13][4];
    #pragma unroll
    for (int t = 0; t < 13; ++t)
        #pragma unroll
        for (int r = 0; r < 4; ++r) dA[t][r] = 0.0f;

    #pragma unroll 1
    for (int ch = 0; ch < 4; ++ch) {
        if (ch) __syncthreads();          // protect prior chunk's smem reads
        // stage Q cols [ch*64 .. +63]
        for (int idx = tid; idx < NROW * 16; idx += 256) {
            const int n = idx >> 4, c4 = (idx & 15) << 2;
            const float4 v = *(const float4*)(qg + n * CDIM + ch * 64 + c4);
            uint4 u;
            u.x = tf32c(v.x); u.y = tf32c(v.y); u.z = tf32c(v.z); u.w = tf32c(v.w);
            *(uint4*)(sm + n * SQS2 + c4) = u;
        }
        // stage W rows [ch*64 .. +63], 104 cols (j=103 zero)
        for (int idx = tid; idx < 64 * 104; idx += 256) {
            const int c = idx / 104;
            const int j = idx - c * 104;
            const float v = (j < JDIM) ? Wwl[(ch * 64 + c) * JDIM + j] : 0.0f;
            sm[K1_SW + idx] = __uint_as_float(tf32c(v));
        }
        __syncthreads();

        if (w < 7) {
            const int r0 = w * 16 + lg;
            const uint32_t* qa = smu + r0 * SQS2 + lt;
            const uint32_t* qb = qa + 8 * SQS2;
            const uint32_t* bp = smu + K1_SW + lt * 104 + lg;
            #pragma unroll
            for (int kt = 0; kt < 8; ++kt) {
                const int kc = kt * 8;
                uint4 a;
                a.x = qa[kc]; a.y = qb[kc]; a.z = qa[kc + 4]; a.w = qb[kc + 4];
                const uint32_t* bk = bp + kc * 104;
                #pragma unroll
                for (int t = 0; t < 13; ++t) {
                    uint2 bb;
                    bb.x = bk[t * 8];
                    bb.y = bk[4 * 104 + t * 8];
                    mma8(dA[t], a, bb);
                }
            }
        }
    }
    __syncthreads();   // all MMA smem reads done; region0 becomes dyBuf

    // epilogue: dy = D + bias (tf32) -> dyBuf [100][108]
    if (w < 7) {
        const int r0 = w * 16 + lg;
        #pragma unroll
        for (int t = 0; t < 13; ++t) {
            const int j0 = t * 8 + 2 * lt;
            const float b0 = sm[K1_BIAS + j0], b1 = sm[K1_BIAS + j0 + 1];
            if (r0 < NROW)
                *(float2*)(sm + r0 * DYS + j0) =
                    make_float2(tf32f(dA[t][0] + b0), tf32f(dA[t][1] + b1));
            if (r0 + 8 < NROW)
                *(float2*)(sm + (r0 + 8) * DYS + j0) =
                    make_float2(tf32f(dA[t][2] + b0), tf32f(dA[t][3] + b1));
        }
    }
    __syncthreads();

    // writeout: pw[b][n][m] = dy[n][3+m] (zero-padded), dw[b][n][k]
    float* pwb = g_pw + (size_t)b * 10816;
    for (int idx = tid; idx < 104 * 26; idx += 256) {
        const int n = idx / 26;
        const int m4 = (idx - n * 26) * 4;
        float4 o;
        o.x = (n < NROW && m4 + 0 < NROW) ? sm[n * DYS + 3 + m4 + 0] : 0.0f;
        o.y = (n < NROW && m4 + 1 < NROW) ? sm[n * DYS + 3 + m4 + 1] : 0.0f;
        o.z = (n < NROW && m4 + 2 < NROW) ? sm[n * DYS + 3 + m4 + 2] : 0.0f;
        o.w = (n < NROW && m4 + 3 < NROW) ? sm[n * DYS + 3 + m4 + 3] : 0.0f;
        *(float4*)(pwb + n * 104 + m4) = o;
    }
    if (tid < NROW) {
        float4 d;
        d.x = sm[tid * DYS + 0];
        d.y = sm[tid * DYS + 1];
        d.z = sm[tid * DYS + 2];
        d.w = 0.0f;
        *(float4*)(g_dw + b * 400 + tid * 4) = d;
    }
}

// ================= K3: out = pw @ depth (c-split), fused conv + LN ==========
// grid 2*B: b = bx>>1, half = bx&1 (cols half*128 .. +127)
// smem: DP [104][136]=14144 (stride 136, mod32=8) | dw 400 @14144
//       mu 112 @14544 | inv 112 @14656 | flag @14768 ; total 14776f = 59,104B -> occ 3
#define DPS2    136
#define K3_DW   14144
#define K3_MU   14544
#define K3_IV   14656
#define K3_FLAG 14768
#define K3_F    14776

__global__ void __launch_bounds__(256, 3)
k3_gemm(const float* __restrict__ value, const float* __restrict__ gamma,
        const float* __restrict__ beta,  float* __restrict__ out)
{
    extern __shared__ float sm[];
    const uint32_t* smu = (const uint32_t*)sm;
    const int bx = blockIdx.x, tid = threadIdx.x;
    const int b = bx >> 1, half = bx & 1, c0 = half << 7;
    const int w = tid >> 5, lane = tid & 31;
    const int lg = lane >> 2, lt = lane & 3;
    const float* vg = value + (size_t)b * (NROW * CDIM);
    float*       og = out   + (size_t)b * (NROW * CDIM);

    // stage dw
    for (int idx = tid; idx < 400; idx += 256)
        sm[K3_DW + idx] = g_dw[b * 400 + idx];
    __syncthreads();

    // conv for this half's c-range: depth[m][cl] (cl = c - c0)
    for (int idx = tid; idx < NROW * 32; idx += 256) {
        const int m = idx >> 5;
        const int cl4 = (idx & 31) << 2;
        const int c4 = c0 + cl4;
        const float* vr = vg + m * CDIM;
        const float d0 = sm[K3_DW + m * 4 + 0];
        const float d1 = sm[K3_DW + m * 4 + 1];
        const float d2 = sm[K3_DW + m * 4 + 2];
        const float4 vc = *(const float4*)(vr + c4);
        const float vl  = (c4 == 0)   ? 0.0f : vr[c4 - 1];
        const float vrt = (c4 == 252) ? 0.0f : vr[c4 + 4];
        uint4 u;
        u.x = tf32c(fmaxf(fmaf(d0, vl,   fmaf(d1, vc.x, d2 * vc.y)), 0.0f));
        u.y = tf32c(fmaxf(fmaf(d0, vc.x, fmaf(d1, vc.y, d2 * vc.z)), 0.0f));
        u.z = tf32c(fmaxf(fmaf(d0, vc.y, fmaf(d1, vc.z, d2 * vc.w)), 0.0f));
        u.w = tf32c(fmaxf(fmaf(d0, vc.z, fmaf(d1, vc.w, d2 * vrt)), 0.0f));
        *(uint4*)(sm + m * DPS2 + cl4) = u;
    }
    for (int idx = tid; idx < 4 * 32; idx += 256) {   // zero K-pad rows m=100..103
        const int m = NROW + (idx >> 5);
        const int cl4 = (idx & 31) << 2;
        *(uint4*)(sm + m * DPS2 + cl4) = make_uint4(0u, 0u, 0u, 0u);
    }
    __syncthreads();

    // MMA: warp w<7 owns rows r0=w*16+lg, r0+8; nb 0..1 (64-col blocks of this half)
    if (w < 7) {
        const int r0 = w * 16 + lg;
        const float* pwb = g_pw + (size_t)b * 10816;
        float s0 = 0.0f, q0 = 0.0f, s1 = 0.0f, q1 = 0.0f;
        #pragma unroll 1
        for (int nb = 0; nb < 2; ++nb) {
            float dC[8][4];
            #pragma unroll
            for (int t = 0; t < 8; ++t)
                #pragma unroll
                for (int r = 0; r < 4; ++r) dC[t][r] = 0.0f;
            const uint32_t* dp = smu + lt * DPS2 + nb * 64 + lg;
            #pragma unroll
            for (int kt = 0; kt < 13; ++kt) {
                const int kc = kt * 8;
                uint4 a;
                a.x = __float_as_uint(pwb[r0 * 104 + kc + lt]);
                a.y = __float_as_uint(pwb[(r0 + 8) * 104 + kc + lt]);
                a.z = __float_as_uint(pwb[r0 * 104 + kc + lt + 4]);
                a.w = __float_as_uint(pwb[(r0 + 8) * 104 + kc + lt + 4]);
                const uint32_t* dk = dp + kc * DPS2;
                #pragma unroll
                for (int t = 0; t < 8; ++t) {
                    uint2 bb;
                    bb.x = dk[t * 8];
                    bb.y = dk[4 * DPS2 + t * 8];
                    mma8(dC[t], a, bb);
                }
            }
            #pragma unroll
            for (int t = 0; t < 8; ++t) {
                const int j0 = c0 + nb * 64 + t * 8 + 2 * lt;
                if (r0 < NROW)
                    *(float2*)(og + r0 * CDIM + j0) = make_float2(dC[t][0], dC[t][1]);
                if (r0 + 8 < NROW)
                    *(float2*)(og + (r0 + 8) * CDIM + j0) = make_float2(dC[t][2], dC[t][3]);
                s0 += dC[t][0] + dC[t][1];
                q0 = fmaf(dC[t][0], dC[t][0], fmaf(dC[t][1], dC[t][1], q0));
                s1 += dC[t][2] + dC[t][3];
                q1 = fmaf(dC[t][2], dC[t][2], fmaf(dC[t][3], dC[t][3], q1));
            }
        }
        s0 += __shfl_xor_sync(~0u, s0, 1); s0 += __shfl_xor_sync(~0u, s0, 2);
        q0 += __shfl_xor_sync(~0u, q0, 1); q0 += __shfl_xor_sync(~0u, q0, 2);
        s1 += __shfl_xor_sync(~0u, s1, 1); s1 += __shfl_xor_sync(~0u, s1, 2);
        q1 += __shfl_xor_sync(~0u, q1, 1); q1 += __shfl_xor_sync(~0u, q1, 2);
        if (lt == 0) {
            const int base = (b * 2 + half) * 112;
            if (r0 < NROW)     { g_ps[base + r0]     = s0; g_pq[base + r0]     = q0; }
            if (r0 + 8 < NROW) { g_ps[base + r0 + 8] = s1; g_pq[base + r0 + 8] = q1; }
        }
    }
    __threadfence();
    __syncthreads();

    // last-CTA-per-batch: combine stats, normalize all 256 cols, reset flag
    if (tid == 0)
        ((int*)sm)[K3_FLAG] = atomicAdd(&g_flag[b], 1);
    __syncthreads();
    if (((int*)sm)[K3_FLAG] == 1) {
        __threadfence();
        if (tid < NROW) {
            const float S  = g_ps[(b * 2) * 112 + tid] + g_ps[(b * 2 + 1) * 112 + tid];
            const float SS = g_pq[(b * 2) * 112 + tid] + g_pq[(b * 2 + 1) * 112 + tid];
            const float mu = S * (1.0f / 256.0f);
            float var = fmaf(-mu, mu, SS * (1.0f / 256.0f));
            var = fmaxf(var, 0.0f);
            sm[K3_MU + tid] = mu;
            sm[K3_IV + tid] = rsqrtf(var + 1e-5f);
        }
        __syncthreads();
        for (int idx = tid; idx < NROW * 64; idx += 256) {
            const int n = idx >> 6;
            const int c4 = (idx & 63) << 2;
            float4 v = *(const float4*)(og + n * CDIM + c4);
            const float mu  = sm[K3_MU + n];
            const float inv = sm[K3_IV + n];
            const float4 g  = *(const float4*)(gamma + c4);
            const float4 bt = *(const float4*)(beta + c4);
            v.x = fmaf((v.x - mu) * inv, g.x, bt.x);
            v.y = fmaf((v.y - mu) * inv, g.y, bt.y);
            v.z = fmaf((v.z - mu) * inv, g.z, bt.z);
            v.w = fmaf((v.w - mu) * inv, g.w, bt.w);
            *(float4*)(og + n * CDIM + c4) = v;
        }
        if (tid == 0) g_flag[b] = 0;   // reset for next graph replay
    }
}

extern "C" void kernel_launch(void* const* d_in, const int* in_sizes, int n_in,
                              void* d_out, int out_size)
{
    const float* query = (const float*)d_in[0];
    const float* value = (const float*)d_in[1];
    const float* Wwl   = (const float*)d_in[2];
    const float* bwl   = (const float*)d_in[3];
    const float* gamma = (const float*)d_in[4];
    const float* beta  = (const float*)d_in[5];
    float* out = (float*)d_out;

    const int B = in_sizes[0] / (NROW * CDIM);   // 512
    cudaFuncSetAttribute(k1_gemm, cudaFuncAttributeMaxDynamicSharedMemorySize,
                         K1_F * (int)sizeof(float));
    cudaFuncSetAttribute(k3_gemm, cudaFuncAttributeMaxDynamicSharedMemorySize,
                         K3_F * (int)sizeof(float));
    k1_gemm<<<B, 256, K1_F * sizeof(float)>>>(query, Wwl, bwl);
    k3_gemm<<<2 * B, 256, K3_F * sizeof(float)>>>(value, gamma, beta, out);
}

// round 13
// speedup vs baseline: 1.2772x; 1.2772x over previous
#include <cuda_runtime.h>
#include <cstdint>

// DySepConvAtten v12: v10 (best: 125us) + vectorized K1 W staging (stride 103).
// K1: dy = Q@W+b -> pw (shifted, padded) + dw scratch.   occ 2
// K3: depth = relu(conv) staged in smem; out = pw@depth; fused LN.  occ 2
#define NROW 100
#define CDIM 256
#define JDIM 103
#define BMAX 512

__device__ float g_pw[BMAX * 104 * 104 + 4096];   // [b][n(104)][m(104)], zero-padded
__device__ float g_dw[BMAX * 100 * 4];            // [b][m][4]

static __device__ __forceinline__ uint32_t tf32c(float f) {
    uint32_t u; asm("cvt.rna.tf32.f32 %0, %1;" : "=r"(u) : "f"(f)); return u;
}
static __device__ __forceinline__ float tf32f(float f) {
    return __uint_as_float(tf32c(f));
}
static __device__ __forceinline__ void mma8(float* d, uint4 a, uint2 b) {
    asm volatile(
        "mma.sync.aligned.m16n8k8.row.col.f32.tf32.tf32.f32 "
        "{%0,%1,%2,%3}, {%4,%5,%6,%7}, {%8,%9}, {%0,%1,%2,%3};"
        : "+f"(d[0]), "+f"(d[1]), "+f"(d[2]), "+f"(d[3])
        : "r"(a.x), "r"(a.y), "r"(a.z), "r"(a.w), "r"(b.x), "r"(b.y));
}

// ================= K1: dy = Q @ W + b  (2 chunks of K=128) =================
// smem: region0 [0..13200): sQ [100][132] (stride 132, mod32=4) / dyBuf [100][108]
//       sW [128][103]+pad = 13216 @13200 (native stride 103)
//       bias 104 @26416 ; total 26520f = 106,080B -> occ 2
#define SQS     132
#define DYS     108
#define K1_SW   13200
#define K1_BIAS 26416
#define K1_F    26520

__global__ void __launch_bounds__(256, 2)
k1_gemm(const float* __restrict__ query, const float* __restrict__ Wwl,
        const float* __restrict__ bwl)
{
    extern __shared__ float sm[];
    const uint32_t* smu = (const uint32_t*)sm;
    const int b = blockIdx.x, tid = threadIdx.x;
    const int w = tid >> 5, lane = tid & 31;
    const int lg = lane >> 2, lt = lane & 3;
    const float* qg = query + (size_t)b * (NROW * CDIM);

    if (tid < 104) sm[K1_BIAS + tid] = (tid < JDIM) ? bwl[tid] : 0.0f;

    float dA[13][4];
    #pragma unroll
    for (int t = 0; t < 13; ++t)
        #pragma unroll
        for (int r = 0; r < 4; ++r) dA[t][r] = 0.0f;

    #pragma unroll 1
    for (int ch = 0; ch < 2; ++ch) {
        if (ch) __syncthreads();   // protect prior chunk's smem reads
        // stage Q cols [ch*128 .. +127] (coalesced float4, tf32)
        for (int idx = tid; idx < NROW * 32; idx += 256) {
            const int n = idx >> 5, c4 = (idx & 31) << 2;
            const float4 v = *(const float4*)(qg + n * CDIM + ch * 128 + c4);
            uint4 u;
            u.x = tf32c(v.x); u.y = tf32c(v.y); u.z = tf32c(v.z); u.w = tf32c(v.w);
            *(uint4*)(sm + n * SQS + c4) = u;
        }
        // stage W rows [ch*128 .. +127] as a LINEAR float4 copy (native stride 103)
        {
            const float4* src = (const float4*)(Wwl + ch * 128 * JDIM);   // 13184 floats, 16B-aligned
            for (int idx = tid; idx < 3296; idx += 256) {
                const float4 v = src[idx];
                uint4 u;
                u.x = tf32c(v.x); u.y = tf32c(v.y); u.z = tf32c(v.z); u.w = tf32c(v.w);
                *(uint4*)(sm + K1_SW + idx * 4) = u;
            }
            if (tid < 32) sm[K1_SW + 13184 + tid] = 0.0f;   // safe pad for j=103 tail reads
        }
        __syncthreads();

        if (w < 7) {
            const int r0 = w * 16 + lg;
            const uint32_t* qa = smu + r0 * SQS + lt;
            const uint32_t* qb = qa + 8 * SQS;
            const uint32_t* bp = smu + K1_SW + lt * JDIM + lg;
            #pragma unroll 4
            for (int kt = 0; kt < 16; ++kt) {
                const int kc = kt * 8;
                uint4 a;
                a.x = qa[kc]; a.y = qb[kc]; a.z = qa[kc + 4]; a.w = qb[kc + 4];
                const uint32_t* bk = bp + kc * JDIM;
                #pragma unroll
                for (int t = 0; t < 13; ++t) {
                    uint2 bb;
                    bb.x = bk[t * 8];
                    bb.y = bk[4 * JDIM + t * 8];
                    mma8(dA[t], a, bb);
                }
            }
        }
    }
    __syncthreads();   // all MMA smem reads done; region0 becomes dyBuf

    // epilogue: dy = D + bias (tf32-rounded) -> dyBuf [100][108]
    if (w < 7) {
        const int r0 = w * 16 + lg;
        #pragma unroll
        for (int t = 0; t < 13; ++t) {
            const int j0 = t * 8 + 2 * lt;
            const float b0 = sm[K1_BIAS + j0], b1 = sm[K1_BIAS + j0 + 1];
            if (r0 < NROW)
                *(float2*)(sm + r0 * DYS + j0) =
                    make_float2(tf32f(dA[t][0] + b0), tf32f(dA[t][1] + b1));
            if (r0 + 8 < NROW)
                *(float2*)(sm + (r0 + 8) * DYS + j0) =
                    make_float2(tf32f(dA[t][2] + b0), tf32f(dA[t][3] + b1));
        }
    }
    __syncthreads();

    // writeout: pw[b][n][m] = dy[n][3+m] (n<100, m<100; else 0), dw[b][n][k]
    float* pwb = g_pw + (size_t)b * 10816;
    for (int idx = tid; idx < 104 * 26; idx += 256) {
        const int n = idx / 26;
        const int m4 = (idx - n * 26) * 4;
        float4 o;
        o.x = (n < NROW && m4 + 0 < NROW) ? sm[n * DYS + 3 + m4 + 0] : 0.0f;
        o.y = (n < NROW && m4 + 1 < NROW) ? sm[n * DYS + 3 + m4 + 1] : 0.0f;
        o.z = (n < NROW && m4 + 2 < NROW) ? sm[n * DYS + 3 + m4 + 2] : 0.0f;
        o.w = (n < NROW && m4 + 3 < NROW) ? sm[n * DYS + 3 + m4 + 3] : 0.0f;
        *(float4*)(pwb + n * 104 + m4) = o;
    }
    if (tid < NROW) {
        float4 d;
        d.x = sm[tid * DYS + 0];
        d.y = sm[tid * DYS + 1];
        d.z = sm[tid * DYS + 2];
        d.w = 0.0f;
        *(float4*)(g_dw + b * 400 + tid * 4) = d;
    }
}

// ================= K3: out = pw @ depth, fused conv + LN =================
// smem: DP [104][264]=27456f (stride 264, mod32=8) | dwS 400f @27456
//       MU 112f @27856 | INV 112f @27968 ; total 28080f = 112,320B -> occ 2
#define DPS   264
#define K3_DW 27456
#define K3_MU 27856
#define K3_IV 27968
#define K3_F  28080

__global__ void __launch_bounds__(256, 2)
k3_gemm(const float* __restrict__ value, const float* __restrict__ gamma,
        const float* __restrict__ beta,  float* __restrict__ out)
{
    extern __shared__ float sm[];
    const uint32_t* smu = (const uint32_t*)sm;
    const int b = blockIdx.x, tid = threadIdx.x;
    const int w = tid >> 5, lane = tid & 31;
    const int lg = lane >> 2, lt = lane & 3;
    const float* vg = value + (size_t)b * (NROW * CDIM);
    float*       og = out   + (size_t)b * (NROW * CDIM);

    // stage dw
    for (int idx = tid; idx < 400; idx += 256)
        sm[K3_DW + idx] = g_dw[b * 400 + idx];
    __syncthreads();

    // conv: depth[m][c] = relu(dw0*v[c-1] + dw1*v[c] + dw2*v[c+1]) (tf32)
    for (int idx = tid; idx < NROW * 64; idx += 256) {
        const int m = idx >> 6;
        const int c4 = (idx & 63) << 2;
        const float* vr = vg + m * CDIM;
        const float d0 = sm[K3_DW + m * 4 + 0];
        const float d1 = sm[K3_DW + m * 4 + 1];
        const float d2 = sm[K3_DW + m * 4 + 2];
        const float4 vc = *(const float4*)(vr + c4);
        const float vl  = (c4 == 0)   ? 0.0f : vr[c4 - 1];
        const float vrt = (c4 == 252) ? 0.0f : vr[c4 + 4];
        uint4 u;
        u.x = tf32c(fmaxf(fmaf(d0, vl,   fmaf(d1, vc.x, d2 * vc.y)), 0.0f));
        u.y = tf32c(fmaxf(fmaf(d0, vc.x, fmaf(d1, vc.y, d2 * vc.z)), 0.0f));
        u.z = tf32c(fmaxf(fmaf(d0, vc.y, fmaf(d1, vc.z, d2 * vc.w)), 0.0f));
        u.w = tf32c(fmaxf(fmaf(d0, vc.z, fmaf(d1, vc.w, d2 * vrt)), 0.0f));
        *(uint4*)(sm + m * DPS + c4) = u;
    }
    for (int idx = tid; idx < 4 * 64; idx += 256) {   // zero K-pad rows m=100..103
        const int m = NROW + (idx >> 6);
        const int c4 = (idx & 63) << 2;
        *(uint4*)(sm + m * DPS + c4) = make_uint4(0u, 0u, 0u, 0u);
    }
    __syncthreads();

    // MMA: warp w (<7) owns m-tile w (rows r0, r0+8); loops nb 0..3 over 64-col blocks.
    if (w < 7) {
        const int r0 = w * 16 + lg;
        const float* pwb = g_pw + (size_t)b * 10816;
        // preload all 13 A-fragments from pw scratch (L2; 52 independent LDGs)
        uint4 af[13];
        #pragma unroll
        for (int kt = 0; kt < 13; ++kt) {
            const int kc = kt * 8;
            af[kt].x = __float_as_uint(pwb[r0 * 104 + kc + lt]);
            af[kt].y = __float_as_uint(pwb[(r0 + 8) * 104 + kc + lt]);
            af[kt].z = __float_as_uint(pwb[r0 * 104 + kc + lt + 4]);
            af[kt].w = __float_as_uint(pwb[(r0 + 8) * 104 + kc + lt + 4]);
        }
        float s0 = 0.0f, q0 = 0.0f, s1 = 0.0f, q1 = 0.0f;
        #pragma unroll 1
        for (int nb = 0; nb < 4; ++nb) {
            float dC[8][4];
            #pragma unroll
            for (int t = 0; t < 8; ++t)
                #pragma unroll
                for (int r = 0; r < 4; ++r) dC[t][r] = 0.0f;
            const uint32_t* dp = smu + lt * DPS + nb * 64 + lg;
            #pragma unroll
            for (int kt = 0; kt < 13; ++kt) {
                const uint32_t* dk = dp + kt * 8 * DPS;
                #pragma unroll
                for (int t = 0; t < 8; ++t) {
                    uint2 bb;
                    bb.x = dk[t * 8];
                    bb.y = dk[4 * DPS + t * 8];
                    mma8(dC[t], af[kt], bb);
                }
            }
            // raw store + LN partials
            #pragma unroll
            for (int t = 0; t < 8; ++t) {
                const int j0 = nb * 64 + t * 8 + 2 * lt;
                if (r0 < NROW)
                    *(float2*)(og + r0 * CDIM + j0) = make_float2(dC[t][0], dC[t][1]);
                if (r0 + 8 < NROW)
                    *(float2*)(og + (r0 + 8) * CDIM + j0) = make_float2(dC[t][2], dC[t][3]);
                s0 += dC[t][0] + dC[t][1];
                q0 = fmaf(dC[t][0], dC[t][0], fmaf(dC[t][1], dC[t][1], q0));
                s1 += dC[t][2] + dC[t][3];
                q1 = fmaf(dC[t][2], dC[t][2], fmaf(dC[t][3], dC[t][3], q1));
            }
        }
        // reduce over lt and publish mu/inv
        s0 += __shfl_xor_sync(~0u, s0, 1); s0 += __shfl_xor_sync(~0u, s0, 2);
        q0 += __shfl_xor_sync(~0u, q0, 1); q0 += __shfl_xor_sync(~0u, q0, 2);
        s1 += __shfl_xor_sync(~0u, s1, 1); s1 += __shfl_xor_sync(~0u, s1, 2);
        q1 += __shfl_xor_sync(~0u, q1, 1); q1 += __shfl_xor_sync(~0u, q1, 2);
        if (lt == 0) {
            if (r0 < NROW) {
                const float mu = s0 * (1.0f / 256.0f);
                float var = fmaf(-mu, mu, q0 * (1.0f / 256.0f));
                var = fmaxf(var, 0.0f);
                sm[K3_MU + r0] = mu;
                sm[K3_IV + r0] = rsqrtf(var + 1e-5f);
            }
            if (r0 + 8 < NROW) {
                const float mu = s1 * (1.0f / 256.0f);
                float var = fmaf(-mu, mu, q1 * (1.0f / 256.0f));
                var = fmaxf(var, 0.0f);
                sm[K3_MU + r0 + 8] = mu;
                sm[K3_IV + r0 + 8] = rsqrtf(var + 1e-5f);
            }
        }
    }
    __syncthreads();

    // in-place normalize (reads raw out from L2)
    for (int idx = tid; idx < NROW * 64; idx += 256) {
        const int n = idx >> 6;
        const int c4 = (idx & 63) << 2;
        float4 v = *(const float4*)(og + n * CDIM + c4);
        const float mu  = sm[K3_MU + n];
        const float inv = sm[K3_IV + n];
        const float4 g  = *(const float4*)(gamma + c4);
        const float4 bt = *(const float4*)(beta + c4);
        v.x = fmaf((v.x - mu) * inv, g.x, bt.x);
        v.y = fmaf((v.y - mu) * inv, g.y, bt.y);
        v.z = fmaf((v.z - mu) * inv, g.z, bt.z);
        v.w = fmaf((v.w - mu) * inv, g.w, bt.w);
        *(float4*)(og + n * CDIM + c4) = v;
    }
}

extern "C" void kernel_launch(void* const* d_in, const int* in_sizes, int n_in,
                              void* d_out, int out_size)
{
    const float* query = (const float*)d_in[0];
    const float* value = (const float*)d_in[1];
    const float* Wwl   = (const float*)d_in[2];
    const float* bwl   = (const float*)d_in[3];
    const float* gamma = (const float*)d_in[4];
    const float* beta  = (const float*)d_in[5];
    float* out = (float*)d_out;

    const int B = in_sizes[0] / (NROW * CDIM);   // 512
    cudaFuncSetAttribute(k1_gemm, cudaFuncAttributeMaxDynamicSharedMemorySize,
                         K1_F * (int)sizeof(float));
    cudaFuncSetAttribute(k3_gemm, cudaFuncAttributeMaxDynamicSharedMemorySize,
                         K3_F * (int)sizeof(float));
    k1_gemm<<<B, 256, K1_F * sizeof(float)>>>(query, Wwl, bwl);
    k3_gemm<<<B, 256, K3_F * sizeof(float)>>>(value, gamma, beta, out);
}

// round 17
// speedup vs baseline: 1.6168x; 1.2660x over previous
#include <cuda_runtime.h>
#include <cuda_fp16.h>
#include <cstdint>

// DySepConvAtten v15: fp16 m16n8k16 mma for both GEMMs (v14 + alignment fix).
// K1: dy = Q@W+b (single K=256 pass) -> pw (half2) / dw (f32) scratch. occ 2
// K3: depth=relu(conv) packed half2 in smem; out = pw@depth; fused LN. occ 3
#define NROW 100
#define CDIM 256
#define JDIM 103
#define BMAX 512

__device__ uint32_t g_pw[BMAX * 104 * 56 + 1024];  // half2 [b][n:104][mp:56]
__device__ float    g_dw[BMAX * 100 * 4];          // [b][m][4]

static __device__ __forceinline__ uint32_t h2u(float lo, float hi) {
    __half2 h = __floats2half2_rn(lo, hi);
    return *(uint32_t*)&h;
}
static __device__ __forceinline__ void mma16(float* d, uint4 a, uint2 b) {
    asm volatile(
        "mma.sync.aligned.m16n8k16.row.col.f32.f16.f16.f32 "
        "{%0,%1,%2,%3}, {%4,%5,%6,%7}, {%8,%9}, {%0,%1,%2,%3};"
        : "+f"(d[0]), "+f"(d[1]), "+f"(d[2]), "+f"(d[3])
        : "r"(a.x), "r"(a.y), "r"(a.z), "r"(a.w), "r"(b.x), "r"(b.y));
}

// ================= K1: dy = Q @ W + b  (K=256, 16 k16-steps) =================
// word layout: sqh [100][132] (stride 132 mod32=4; c-pairs 0..127) / dyBuf [100][108] f32
//              swh [128][104] @13200 (stride 104 mod32=8; rows = c-pairs, cols j)
//              bias 104 f32 @26512 ; total 26616 words = 106,464B -> occ 2
#define SQHS    132
#define DYS     108
#define K1_SWH  13200
#define K1_BIAS 26512
#define K1_F    26616

__global__ void __launch_bounds__(256, 2)
k1_gemm(const float* __restrict__ query, const float* __restrict__ Wwl,
        const float* __restrict__ bwl)
{
    extern __shared__ float sm[];
    uint32_t* smw = (uint32_t*)sm;
    const int b = blockIdx.x, tid = threadIdx.x;
    const int w = tid >> 5, lane = tid & 31;
    const int lg = lane >> 2, lt = lane & 3;
    const float* qg = query + (size_t)b * (NROW * CDIM);

    if (tid < 104) sm[K1_BIAS + tid] = (tid < JDIM) ? bwl[tid] : 0.0f;

    // stage sqh: pairs along c (k-dim); [n][cp] = half2(Q[n][2cp], Q[n][2cp+1])
    for (int idx = tid; idx < NROW * 32; idx += 256) {
        const int n = idx >> 5, c8 = (idx & 31) << 3;   // 8 floats -> 4 words
        const float4 v0 = *(const float4*)(qg + n * CDIM + c8);
        const float4 v1 = *(const float4*)(qg + n * CDIM + c8 + 4);
        uint4 u;
        u.x = h2u(v0.x, v0.y); u.y = h2u(v0.z, v0.w);
        u.z = h2u(v1.x, v1.y); u.w = h2u(v1.z, v1.w);
        *(uint4*)(smw + n * SQHS + (c8 >> 1)) = u;
    }
    // stage swh: [cp][j] = half2(W[2cp][j], W[2cp+1][j]), j=103 -> 0
    // even row: float2 (8B-aligned: even element offset); odd row: scalar loads.
    for (int idx = tid; idx < 128 * 52; idx += 256) {
        const int cp = idx / 52, j2 = idx - cp * 52;
        const float* r0p = Wwl + (2 * cp) * JDIM;
        const float* r1p = r0p + JDIM;
        float a0, a1, b0, b1;
        if (j2 < 51) {
            const float2 fa = *(const float2*)(r0p + j2 * 2);
            a0 = fa.x; a1 = fa.y;
            b0 = r1p[j2 * 2];          // odd base -> scalar (4B-aligned only)
            b1 = r1p[j2 * 2 + 1];
        } else {           // j = 102, 103(pad)
            a0 = r0p[102]; a1 = 0.0f; b0 = r1p[102]; b1 = 0.0f;
        }
        uint2 u = make_uint2(h2u(a0, b0), h2u(a1, b1));
        *(uint2*)(smw + K1_SWH + cp * 104 + j2 * 2) = u;
    }
    __syncthreads();

    float dA[13][4];
    #pragma unroll
    for (int t = 0; t < 13; ++t)
        #pragma unroll
        for (int r = 0; r < 4; ++r) dA[t][r] = 0.0f;

    if (w < 7) {
        const int r0 = w * 16 + lg;
        const uint32_t* qa = smw + r0 * SQHS + lt;
        const uint32_t* qb = qa + 8 * SQHS;
        const uint32_t* bp = smw + K1_SWH + lt * 104 + lg;
        #pragma unroll 4
        for (int kt = 0; kt < 16; ++kt) {
            const int kp = kt * 8;
            uint4 a;
            a.x = qa[kp]; a.y = qb[kp]; a.z = qa[kp + 4]; a.w = qb[kp + 4];
            const uint32_t* bk = bp + kp * 104;
            #pragma unroll
            for (int t = 0; t < 13; ++t) {
                uint2 bb;
                bb.x = bk[t * 8];
                bb.y = bk[4 * 104 + t * 8];
                mma16(dA[t], a, bb);
            }
        }
    }
    __syncthreads();   // MMA smem reads done; sqh region becomes dyBuf (f32)

    // epilogue: dy = D + bias (full f32) -> dyBuf [100][108]
    if (w < 7) {
        const int r0 = w * 16 + lg;
        #pragma unroll
        for (int t = 0; t < 13; ++t) {
            const int j0 = t * 8 + 2 * lt;
            const float b0 = sm[K1_BIAS + j0], b1 = sm[K1_BIAS + j0 + 1];
            if (r0 < NROW)
                *(float2*)(sm + r0 * DYS + j0) = make_float2(dA[t][0] + b0, dA[t][1] + b1);
            if (r0 + 8 < NROW)
                *(float2*)(sm + (r0 + 8) * DYS + j0) = make_float2(dA[t][2] + b0, dA[t][3] + b1);
        }
    }
    __syncthreads();

    // writeout: pwh[b][n][mp] = half2(dy[n][3+2mp], dy[n][4+2mp]); pads zero
    uint32_t* pwb = g_pw + (size_t)b * 5824;
    for (int idx = tid; idx < 104 * 56; idx += 256) {
        const int n = idx / 56, mp = idx - n * 56;
        uint32_t v = 0u;
        if (n < NROW && mp < 50)
            v = h2u(sm[n * DYS + 3 + 2 * mp], sm[n * DYS + 4 + 2 * mp]);
        pwb[idx] = v;
    }
    if (tid < NROW) {
        float4 d;
        d.x = sm[tid * DYS + 0];
        d.y = sm[tid * DYS + 1];
        d.z = sm[tid * DYS + 2];
        d.w = 0.0f;
        *(float4*)(g_dw + b * 400 + tid * 4) = d;
    }
}

// ================= K3: out = pw @ depth, fused conv + LN =================
// words: pairbuf [56][264] @0 (stride 264 mod32=8; rows = m-pairs, cols c)
//        dw 400 f32 @14784 | MU 112 @15184 | IV 112 @15296 ; 15408 words = 61,632B -> occ 3
#define PBS   264
#define K3_DW 14784
#define K3_MU 15184
#define K3_IV 15296
#define K3_F  15408

__global__ void __launch_bounds__(256, 3)
k3_gemm(const float* __restrict__ value, const float* __restrict__ gamma,
        const float* __restrict__ beta,  float* __restrict__ out)
{
    extern __shared__ float sm[];
    uint32_t* smw = (uint32_t*)sm;
    const int b = blockIdx.x, tid = threadIdx.x;
    const int w = tid >> 5, lane = tid & 31;
    const int lg = lane >> 2, lt = lane & 3;
    const float* vg = value + (size_t)b * (NROW * CDIM);
    float*       og = out   + (size_t)b * (NROW * CDIM);

    for (int idx = tid; idx < 400; idx += 256)
        sm[K3_DW + idx] = g_dw[b * 400 + idx];
    __syncthreads();

    // conv -> pairbuf[p][c] = half2(depth[2p][c], depth[2p+1][c])
    for (int idx = tid; idx < 50 * 64; idx += 256) {
        const int p = idx >> 6;
        const int c4 = (idx & 63) << 2;
        const int m0 = 2 * p;
        const float* vr0 = vg + m0 * CDIM;
        const float* vr1 = vr0 + CDIM;
        const float e00 = sm[K3_DW + m0 * 4 + 0], e01 = sm[K3_DW + m0 * 4 + 1], e02 = sm[K3_DW + m0 * 4 + 2];
        const float e10 = sm[K3_DW + m0 * 4 + 4], e11 = sm[K3_DW + m0 * 4 + 5], e12 = sm[K3_DW + m0 * 4 + 6];
        const float4 v0 = *(const float4*)(vr0 + c4);
        const float4 v1 = *(const float4*)(vr1 + c4);
        const float l0 = (c4 == 0)   ? 0.0f : vr0[c4 - 1];
        const float r0e = (c4 == 252) ? 0.0f : vr0[c4 + 4];
        const float l1 = (c4 == 0)   ? 0.0f : vr1[c4 - 1];
        const float r1e = (c4 == 252) ? 0.0f : vr1[c4 + 4];
        const float o0x = fmaxf(fmaf(e00, l0,   fmaf(e01, v0.x, e02 * v0.y)), 0.0f);
        const float o0y = fmaxf(fmaf(e00, v0.x, fmaf(e01, v0.y, e02 * v0.z)), 0.0f);
        const float o0z = fmaxf(fmaf(e00, v0.y, fmaf(e01, v0.z, e02 * v0.w)), 0.0f);
        const float o0w = fmaxf(fmaf(e00, v0.z, fmaf(e01, v0.w, e02 * r0e)), 0.0f);
        const float o1x = fmaxf(fmaf(e10, l1,   fmaf(e11, v1.x, e12 * v1.y)), 0.0f);
        const float o1y = fmaxf(fmaf(e10, v1.x, fmaf(e11, v1.y, e12 * v1.z)), 0.0f);
        const float o1z = fmaxf(fmaf(e10, v1.y, fmaf(e11, v1.z, e12 * v1.w)), 0.0f);
        const float o1w = fmaxf(fmaf(e10, v1.z, fmaf(e11, v1.w, e12 * r1e)), 0.0f);
        uint4 u;
        u.x = h2u(o0x, o1x); u.y = h2u(o0y, o1y);
        u.z = h2u(o0z, o1z); u.w = h2u(o0w, o1w);
        *(uint4*)(smw + p * PBS + c4) = u;
    }
    for (int idx = tid; idx < 6 * 64; idx += 256) {   // zero k-pad pairs p=50..55
        const int p = 50 + (idx >> 6);
        const int c4 = (idx & 63) << 2;
        *(uint4*)(smw + p * PBS + c4) = make_uint4(0u, 0u, 0u, 0u);
    }
    __syncthreads();

    if (w < 7) {
        const int r0 = w * 16 + lg;
        const uint32_t* pwb = g_pw + (size_t)b * 5824;
        // preload all 7 A-fragments (28 independent LDG.32 from L2)
        uint4 af[7];
        #pragma unroll
        for (int kt = 0; kt < 7; ++kt) {
            const int kp = kt * 8;
            af[kt].x = pwb[r0 * 56 + kp + lt];
            af[kt].y = pwb[(r0 + 8) * 56 + kp + lt];
            af[kt].z = pwb[r0 * 56 + kp + lt + 4];
            af[kt].w = pwb[(r0 + 8) * 56 + kp + lt + 4];
        }
        float s0 = 0.0f, q0 = 0.0f, s1 = 0.0f, q1 = 0.0f;
        #pragma unroll 1
        for (int nb = 0; nb < 4; ++nb) {
            float dC[8][4];
            #pragma unroll
            for (int t = 0; t < 8; ++t)
                #pragma unroll
                for (int r = 0; r < 4; ++r) dC[t][r] = 0.0f;
            const uint32_t* dp = smw + lt * PBS + nb * 64 + lg;
            #pragma unroll
            for (int kt = 0; kt < 7; ++kt) {
                const uint32_t* dk = dp + kt * 8 * PBS;
                #pragma unroll
                for (int t = 0; t < 8; ++t) {
                    uint2 bb;
                    bb.x = dk[t * 8];
                    bb.y = dk[4 * PBS + t * 8];
                    mma16(dC[t], af[kt], bb);
                }
            }
            #pragma unroll
            for (int t = 0; t < 8; ++t) {
                const int j0 = nb * 64 + t * 8 + 2 * lt;
                if (r0 < NROW)
                    *(float2*)(og + r0 * CDIM + j0) = make_float2(dC[t][0], dC[t][1]);
                if (r0 + 8 < NROW)
                    *(float2*)(og + (r0 + 8) * CDIM + j0) = make_float2(dC[t][2], dC[t][3]);
                s0 += dC[t][0] + dC[t][1];
                q0 = fmaf(dC[t][0], dC[t][0], fmaf(dC[t][1], dC[t][1], q0));
                s1 += dC[t][2] + dC[t][3];
                q1 = fmaf(dC[t][2], dC[t][2], fmaf(dC[t][3], dC[t][3], q1));
            }
        }
        s0 += __shfl_xor_sync(~0u, s0, 1); s0 += __shfl_xor_sync(~0u, s0, 2);
        q0 += __shfl_xor_sync(~0u, q0, 1); q0 += __shfl_xor_sync(~0u, q0, 2);
        s1 += __shfl_xor_sync(~0u, s1, 1); s1 += __shfl_xor_sync(~0u, s1, 2);
        q1 += __shfl_xor_sync(~0u, q1, 1); q1 += __shfl_xor_sync(~0u, q1, 2);
        if (lt == 0) {
            if (r0 < NROW) {
                const float mu = s0 * (1.0f / 256.0f);
                float var = fmaf(-mu, mu, q0 * (1.0f / 256.0f));
                var = fmaxf(var, 0.0f);
                sm[K3_MU + r0] = mu;
                sm[K3_IV + r0] = rsqrtf(var + 1e-5f);
            }
            if (r0 + 8 < NROW) {
                const float mu = s1 * (1.0f / 256.0f);
                float var = fmaf(-mu, mu, q1 * (1.0f / 256.0f));
                var = fmaxf(var, 0.0f);
                sm[K3_MU + r0 + 8] = mu;
                sm[K3_IV + r0 + 8] = rsqrtf(var + 1e-5f);
            }
        }
    }
    __syncthreads();

    // in-place normalize (L2 round trip)
    for (int idx = tid; idx < NROW * 64; idx += 256) {
        const int n = idx >> 6;
        const int c4 = (idx & 63) << 2;
        float4 v = *(const float4*)(og + n * CDIM + c4);
        const float mu  = sm[K3_MU + n];
        const float inv = sm[K3_IV + n];
        const float4 g  = *(const float4*)(gamma + c4);
        const float4 bt = *(const float4*)(beta + c4);
        v.x = fmaf((v.x - mu) * inv, g.x, bt.x);
        v.y = fmaf((v.y - mu) * inv, g.y, bt.y);
        v.z = fmaf((v.z - mu) * inv, g.z, bt.z);
        v.w = fmaf((v.w - mu) * inv, g.w, bt.w);
        *(float4*)(og + n * CDIM + c4) = v;
    }
}

extern "C" void kernel_launch(void* const* d_in, const int* in_sizes, int n_in,
                              void* d_out, int out_size)
{
    const float* query = (const float*)d_in[0];
    const float* value = (const float*)d_in[1];
    const float* Wwl   = (const float*)d_in[2];
    const float* bwl   = (const float*)d_in[3];
    const float* gamma = (const float*)d_in[4];
    const float* beta  = (const float*)d_in[5];
    float* out = (float*)d_out;

    const int B = in_sizes[0] / (NROW * CDIM);   // 512
    cudaFuncSetAttribute(k1_gemm, cudaFuncAttributeMaxDynamicSharedMemorySize,
                         K1_F * (int)sizeof(float));
    cudaFuncSetAttribute(k3_gemm, cudaFuncAttributeMaxDynamicSharedMemorySize,
                         K3_F * (int)sizeof(float));
    k1_gemm<<<B, 256, K1_F * sizeof(float)>>>(query, Wwl, bwl);
    k3_gemm<<<B, 256, K3_F * sizeof(float)>>>(value, gamma, beta, out);
}